// round 3
// baseline (speedup 1.0000x reference)
#include <cuda_runtime.h>
#include <math.h>

#define BATCH   2048
#define NPIX    784
#define NMID    783      // number of mid cores
#define NSEG    16
#define LSEG    49       // NSEG*LSEG = 784 >= 783 (1 identity pad)
#define UPB     64       // batch units per block (phase 1)
#define T1      128      // threads per block (phase 1): 2 threads per unit

// 4x pre-scale keeps segment-product norms in mid fp32 range (avoids the
// denormal-underflow -> EPS-clamp bias that broke round 2).
#define MSCALE      4.0f
#define SEG_LOGCOMP 67.92842369489701f   // LSEG * ln(4), subtracted exactly

typedef unsigned long long u64;

// Scratch: per (segment, batch) normalized 10x10 product + log norm
__device__ __align__(16) float g_G[(size_t)NSEG * BATCH * 100];  // [seg][b][l*10+h]
__device__ float g_logn[NSEG * BATCH];                            // [seg][b]

// ---- packed f32x2 helpers (FFMA2 path; see SASS_QUICKREF) ----
__device__ __forceinline__ u64 ffma2(u64 a, u64 b, u64 c) {
    u64 d; asm("fma.rn.f32x2 %0, %1, %2, %3;" : "=l"(d) : "l"(a), "l"(b), "l"(c));
    return d;
}
__device__ __forceinline__ u64 fmul2(u64 a, u64 b) {
    u64 d; asm("mul.rn.f32x2 %0, %1, %2;" : "=l"(d) : "l"(a), "l"(b));
    return d;
}
__device__ __forceinline__ u64 pk2(float lo, float hi) {
    u64 r; asm("mov.b64 %0, {%1, %2};" : "=l"(r) : "f"(lo), "f"(hi));
    return r;
}
__device__ __forceinline__ void upk2(u64 v, float& lo, float& hi) {
    asm("mov.b64 {%0, %1}, %2;" : "=f"(lo), "=f"(hi) : "l"(v));
}

// One chain step: Q = P * M (this thread's 5 rows), M[k][h] = A[k][h] + x*D[k][h].
// s points at this step's staged data: 10 rows of 24 floats:
//   [k*24 + 0..9] = A row (pre-scaled), [k*24 + 12..21] = D row (pre-scaled).
// P, Q hold 5 rows x 5 float2-pairs each.
__device__ __forceinline__ void stepmul(const float* __restrict__ s, u64 xx,
                                        const u64 (&P)[5][5], u64 (&Q)[5][5]) {
    #pragma unroll
    for (int kp = 0; kp < 5; ++kp) {
        const u64* a0 = reinterpret_cast<const u64*>(s + (2 * kp) * 24);
        const u64* d0 = reinterpret_cast<const u64*>(s + (2 * kp) * 24 + 12);
        const u64* a1 = reinterpret_cast<const u64*>(s + (2 * kp + 1) * 24);
        const u64* d1 = reinterpret_cast<const u64*>(s + (2 * kp + 1) * 24 + 12);
        u64 m0[5], m1[5];
        #pragma unroll
        for (int h = 0; h < 5; ++h) {
            m0[h] = ffma2(xx, d0[h], a0[h]);
            m1[h] = ffma2(xx, d1[h], a1[h]);
        }
        #pragma unroll
        for (int l = 0; l < 5; ++l) {
            float p0, p1;
            upk2(P[l][kp], p0, p1);
            const u64 pp0 = pk2(p0, p0);
            const u64 pp1 = pk2(p1, p1);
            if (kp == 0) {
                #pragma unroll
                for (int h = 0; h < 5; ++h) Q[l][h] = fmul2(pp0, m0[h]);
            } else {
                #pragma unroll
                for (int h = 0; h < 5; ++h) Q[l][h] = ffma2(pp0, m0[h], Q[l][h]);
            }
            #pragma unroll
            for (int h = 0; h < 5; ++h) Q[l][h] = ffma2(pp1, m1[h], Q[l][h]);
        }
    }
}

// Phase 1: per (batch, segment) compute normalized product of the segment's
// matrices. grid = (NSEG, BATCH/UPB), block = T1. Thread pair (2*u, 2*u+1)
// owns rows 0-4 / 5-9 of the running product for batch unit u.
__global__ void __launch_bounds__(T1, 3)
phase1(const float* __restrict__ x, const float* __restrict__ cm) {
    __shared__ __align__(16) float sAD[LSEG * 240];

    const int seg = blockIdx.x;
    const int n0  = seg * LSEG;

    // Stage MSCALE*A and MSCALE*(B-A); pad with MSCALE*identity beyond NMID.
    for (int idx = threadIdx.x; idx < LSEG * 200; idx += T1) {
        const int step = idx / 200;
        const int r    = idx % 200;
        const int k    = r / 20;
        const int j    = r % 20;          // 0..9 -> A[h], 10..19 -> D[h]
        const int n    = n0 + step;
        float val;
        if (n < NMID) {
            const int base = ((n * 10 + k) * 2) * 10;   // f=0 row
            if (j < 10) val = MSCALE * cm[base + j];
            else        val = MSCALE * (cm[base + 10 + (j - 10)] - cm[base + (j - 10)]);
        } else {
            val = (j < 10) ? ((j == k) ? MSCALE : 0.0f) : 0.0f;  // scaled identity pad
        }
        sAD[step * 240 + k * 24 + ((j < 10) ? j : (j - 10 + 12))] = val;
    }
    __syncthreads();

    const int t    = threadIdx.x;
    const int unit = t >> 1;
    const int half = t & 1;
    const int b    = blockIdx.y * UPB + unit;
    const float* xb = x + (size_t)b * NPIX;

    u64 P[5][5], Q[5][5];

    // Load the segment's first matrix (rows half*5 .. half*5+4) directly as P.
    {
        const float xv = xb[min(n0 + 1, NPIX - 1)];
        const u64 xx = pk2(xv, xv);
        #pragma unroll
        for (int l = 0; l < 5; ++l) {
            const u64* ar = reinterpret_cast<const u64*>(sAD + (half * 5 + l) * 24);
            const u64* dr = reinterpret_cast<const u64*>(sAD + (half * 5 + l) * 24 + 12);
            #pragma unroll
            for (int hp = 0; hp < 5; ++hp) P[l][hp] = ffma2(xx, dr[hp], ar[hp]);
        }
    }

    // 48 more multiplies (even count -> result lands back in P). x prefetched.
    float xc = xb[min(n0 + 2, NPIX - 1)];
    #pragma unroll 1
    for (int st = 1; st < LSEG; st += 2) {
        const float xn1 = xb[min(n0 + st + 2, NPIX - 1)];
        const float xn2 = xb[min(n0 + st + 3, NPIX - 1)];
        stepmul(sAD + st * 240, pk2(xc, xc), P, Q);
        stepmul(sAD + (st + 1) * 240, pk2(xn1, xn1), Q, P);
        xc = xn2;
    }

    // Frobenius norm over both halves (pair reduction), normalize, store.
    u64 ss2 = 0ull;   // (0.0f, 0.0f)
    #pragma unroll
    for (int l = 0; l < 5; ++l)
        #pragma unroll
        for (int hp = 0; hp < 5; ++hp) ss2 = ffma2(P[l][hp], P[l][hp], ss2);
    float slo, shi;
    upk2(ss2, slo, shi);
    float ss = slo + shi;
    ss += __shfl_xor_sync(0xffffffffu, ss, 1);
    ss = fmaxf(ss, 1e-24f);

    const float inv = rsqrtf(ss);
    const u64 ii = pk2(inv, inv);

    float* gp = g_G + ((size_t)seg * BATCH + b) * 100 + half * 50;
    #pragma unroll
    for (int l = 0; l < 5; ++l)
        #pragma unroll
        for (int hp = 0; hp < 5; ++hp)
            *reinterpret_cast<u64*>(gp + l * 10 + 2 * hp) = fmul2(P[l][hp], ii);
    if (half == 0)
        g_logn[seg * BATCH + b] = 0.5f * __logf(ss) - SEG_LOGCOMP;
}

// Phase 2: per batch, run head vector through the NSEG segment matrices,
// accumulate logs, project onto classifier.
__global__ void __launch_bounds__(256)
phase2(const float* __restrict__ x, const float* __restrict__ core0,
       const float* __restrict__ cls, float* __restrict__ out) {
    const int b = blockIdx.x * blockDim.x + threadIdx.x;
    if (b >= BATCH) return;

    float v[10];
    const float x0 = x[(size_t)b * NPIX];
    #pragma unroll
    for (int h = 0; h < 10; ++h)
        v[h] = fmaf(x0, core0[10 + h] - core0[h], core0[h]);

    float logtot = 0.0f;

    #pragma unroll 1
    for (int s = 0; s < NSEG; ++s) {
        const float2* g2 = reinterpret_cast<const float2*>(
            g_G + ((size_t)s * BATCH + b) * 100);
        float w[10];
        #pragma unroll
        for (int h = 0; h < 10; ++h) w[h] = 0.0f;
        #pragma unroll
        for (int l = 0; l < 10; ++l) {
            const float vl = v[l];
            #pragma unroll
            for (int hp = 0; hp < 5; ++hp) {
                const float2 gv = g2[l * 5 + hp];
                w[2 * hp]     = fmaf(vl, gv.x, w[2 * hp]);
                w[2 * hp + 1] = fmaf(vl, gv.y, w[2 * hp + 1]);
            }
        }
        float ss = 0.0f;
        #pragma unroll
        for (int h = 0; h < 10; ++h) ss = fmaf(w[h], w[h], ss);
        ss = fmaxf(ss, 1e-24f);
        const float inv = rsqrtf(ss);
        logtot += 0.5f * __logf(ss) + g_logn[s * BATCH + b];
        #pragma unroll
        for (int h = 0; h < 10; ++h) v[h] = w[h] * inv;
    }

    #pragma unroll
    for (int o = 0; o < 10; ++o) {
        float acc = 0.0f;
        #pragma unroll
        for (int h = 0; h < 10; ++h) acc = fmaf(v[h], cls[o * 10 + h], acc);
        out[(size_t)b * 10 + o] = acc + logtot;
    }
}

extern "C" void kernel_launch(void* const* d_in, const int* in_sizes, int n_in,
                              void* d_out, int out_size) {
    const float* x     = (const float*)d_in[0];   // (2048, 784)
    const float* core0 = (const float*)d_in[1];   // (1, 2, 10)
    const float* cm    = (const float*)d_in[2];   // (783, 10, 2, 10)
    const float* cls   = (const float*)d_in[3];   // (10, 10)
    float* out = (float*)d_out;                   // (2048, 10)

    dim3 g1(NSEG, BATCH / UPB);
    phase1<<<g1, T1>>>(x, cm);
    phase2<<<(BATCH + 255) / 256, 256>>>(x, core0, cls, out);
}

// round 4
// speedup vs baseline: 1.0734x; 1.0734x over previous
#include <cuda_runtime.h>
#include <math.h>

#define BATCH   2048
#define NPIX    784
#define NMID    783      // number of mid cores
#define NSEG    16
#define LSEG    49       // NSEG*LSEG = 784 >= 783 (1 identity pad)
#define UPB     64       // batch units per block (phase 1)
#define T1      128      // threads per block (phase 1): 2 threads per unit
#define CB      4        // batches (warps) per block in combine

// 4x pre-scale keeps segment-product norms in mid fp32 range (avoids the
// denormal-underflow -> EPS-clamp bias that broke round 2).
#define MSCALE      4.0f
#define SEG_LOGCOMP 67.92842369489701f   // LSEG * ln(4), subtracted exactly

typedef unsigned long long u64;

// Scratch: per (segment, batch) normalized 10x10 product + log norm
__device__ __align__(16) float g_G[(size_t)NSEG * BATCH * 100];  // [seg][b][l*10+h]
__device__ float g_logn[NSEG * BATCH];                            // [seg][b]

// ---- packed f32x2 helpers (FFMA2 path; see SASS_QUICKREF) ----
__device__ __forceinline__ u64 ffma2(u64 a, u64 b, u64 c) {
    u64 d; asm("fma.rn.f32x2 %0, %1, %2, %3;" : "=l"(d) : "l"(a), "l"(b), "l"(c));
    return d;
}
__device__ __forceinline__ u64 fmul2(u64 a, u64 b) {
    u64 d; asm("mul.rn.f32x2 %0, %1, %2;" : "=l"(d) : "l"(a), "l"(b));
    return d;
}
__device__ __forceinline__ u64 pk2(float lo, float hi) {
    u64 r; asm("mov.b64 %0, {%1, %2};" : "=l"(r) : "f"(lo), "f"(hi));
    return r;
}
__device__ __forceinline__ void upk2(u64 v, float& lo, float& hi) {
    asm("mov.b64 {%0, %1}, %2;" : "=f"(lo), "=f"(hi) : "l"(v));
}

// One chain step: Q = P * M (this thread's 5 rows), M[k][h] = A[k][h] + x*D[k][h].
__device__ __forceinline__ void stepmul(const float* __restrict__ s, u64 xx,
                                        const u64 (&P)[5][5], u64 (&Q)[5][5]) {
    #pragma unroll
    for (int kp = 0; kp < 5; ++kp) {
        const u64* a0 = reinterpret_cast<const u64*>(s + (2 * kp) * 24);
        const u64* d0 = reinterpret_cast<const u64*>(s + (2 * kp) * 24 + 12);
        const u64* a1 = reinterpret_cast<const u64*>(s + (2 * kp + 1) * 24);
        const u64* d1 = reinterpret_cast<const u64*>(s + (2 * kp + 1) * 24 + 12);
        u64 m0[5], m1[5];
        #pragma unroll
        for (int h = 0; h < 5; ++h) {
            m0[h] = ffma2(xx, d0[h], a0[h]);
            m1[h] = ffma2(xx, d1[h], a1[h]);
        }
        #pragma unroll
        for (int l = 0; l < 5; ++l) {
            float p0, p1;
            upk2(P[l][kp], p0, p1);
            const u64 pp0 = pk2(p0, p0);
            const u64 pp1 = pk2(p1, p1);
            if (kp == 0) {
                #pragma unroll
                for (int h = 0; h < 5; ++h) Q[l][h] = fmul2(pp0, m0[h]);
            } else {
                #pragma unroll
                for (int h = 0; h < 5; ++h) Q[l][h] = ffma2(pp0, m0[h], Q[l][h]);
            }
            #pragma unroll
            for (int h = 0; h < 5; ++h) Q[l][h] = ffma2(pp1, m1[h], Q[l][h]);
        }
    }
}

// Phase 1: per (batch, segment) normalized product of the segment's matrices.
__global__ void __launch_bounds__(T1, 3)
phase1(const float* __restrict__ x, const float* __restrict__ cm) {
    __shared__ __align__(16) float sAD[LSEG * 240];

    const int seg = blockIdx.x;
    const int n0  = seg * LSEG;

    // Stage MSCALE*A and MSCALE*(B-A); pad with MSCALE*identity beyond NMID.
    for (int idx = threadIdx.x; idx < LSEG * 200; idx += T1) {
        const int step = idx / 200;
        const int r    = idx % 200;
        const int k    = r / 20;
        const int j    = r % 20;          // 0..9 -> A[h], 10..19 -> D[h]
        const int n    = n0 + step;
        float val;
        if (n < NMID) {
            const int base = ((n * 10 + k) * 2) * 10;   // f=0 row
            if (j < 10) val = MSCALE * cm[base + j];
            else        val = MSCALE * (cm[base + 10 + (j - 10)] - cm[base + (j - 10)]);
        } else {
            val = (j < 10) ? ((j == k) ? MSCALE : 0.0f) : 0.0f;  // scaled identity pad
        }
        sAD[step * 240 + k * 24 + ((j < 10) ? j : (j - 10 + 12))] = val;
    }
    __syncthreads();

    const int t    = threadIdx.x;
    const int unit = t >> 1;
    const int half = t & 1;
    const int b    = blockIdx.y * UPB + unit;
    const float* xb = x + (size_t)b * NPIX;

    u64 P[5][5], Q[5][5];

    {
        const float xv = xb[min(n0 + 1, NPIX - 1)];
        const u64 xx = pk2(xv, xv);
        #pragma unroll
        for (int l = 0; l < 5; ++l) {
            const u64* ar = reinterpret_cast<const u64*>(sAD + (half * 5 + l) * 24);
            const u64* dr = reinterpret_cast<const u64*>(sAD + (half * 5 + l) * 24 + 12);
            #pragma unroll
            for (int hp = 0; hp < 5; ++hp) P[l][hp] = ffma2(xx, dr[hp], ar[hp]);
        }
    }

    float xc = xb[min(n0 + 2, NPIX - 1)];
    #pragma unroll 1
    for (int st = 1; st < LSEG; st += 2) {
        const float xn1 = xb[min(n0 + st + 2, NPIX - 1)];
        const float xn2 = xb[min(n0 + st + 3, NPIX - 1)];
        stepmul(sAD + st * 240, pk2(xc, xc), P, Q);
        stepmul(sAD + (st + 1) * 240, pk2(xn1, xn1), Q, P);
        xc = xn2;
    }

    u64 ss2 = 0ull;
    #pragma unroll
    for (int l = 0; l < 5; ++l)
        #pragma unroll
        for (int hp = 0; hp < 5; ++hp) ss2 = ffma2(P[l][hp], P[l][hp], ss2);
    float slo, shi;
    upk2(ss2, slo, shi);
    float ss = slo + shi;
    ss += __shfl_xor_sync(0xffffffffu, ss, 1);
    ss = fmaxf(ss, 1e-24f);

    const float inv = rsqrtf(ss);
    const u64 ii = pk2(inv, inv);

    float* gp = g_G + ((size_t)seg * BATCH + b) * 100 + half * 50;
    #pragma unroll
    for (int l = 0; l < 5; ++l)
        #pragma unroll
        for (int hp = 0; hp < 5; ++hp)
            *reinterpret_cast<u64*>(gp + l * 10 + 2 * hp) = fmul2(P[l][hp], ii);
    if (half == 0)
        g_logn[seg * BATCH + b] = 0.5f * __logf(ss) - SEG_LOGCOMP;
}

// Combine: one warp per batch. Binary-tree reduction of the 16 segment
// matrices (16->8->4->2->1 10x10 matmuls in shared), then head apply +
// classifier. Replaces the serial 16-step phase2 (was 60us at occ 12.5%).
__global__ void __launch_bounds__(CB * 32)
combine(const float* __restrict__ x, const float* __restrict__ core0,
        const float* __restrict__ cls, float* __restrict__ out) {
    __shared__ float sG[CB][24][100];   // slots 0..15 in, 16..23 + 0..6 tree
    __shared__ float sW[CB][10];

    const int w    = threadIdx.x >> 5;
    const int lane = threadIdx.x & 31;
    const int b    = blockIdx.x * CB + w;

    float logacc = 0.0f;

    // Load 16 segment matrices + their logs.
    #pragma unroll
    for (int s = 0; s < NSEG; ++s) {
        const float* src = g_G + ((size_t)s * BATCH + b) * 100;
        #pragma unroll
        for (int i = lane; i < 100; i += 32) sG[w][s][i] = src[i];
    }
    if (lane < NSEG) logacc = g_logn[lane * BATCH + b];
    __syncwarp();

    // Tree levels: (in, out, count): (0->16, 8), (16->0, 4), (0->4, 2), (4->6, 1)
    const int in0[4]  = {0, 16, 0, 4};
    const int out0[4] = {16, 0, 4, 6};
    const int cnt[4]  = {8, 4, 2, 1};

    #pragma unroll
    for (int lev = 0; lev < 4; ++lev) {
        const int p  = lane >> 2;
        const int lg = lane & 3;
        if (p < cnt[lev]) {
            const unsigned gm = 0xFu << (lane & ~3);
            const float* A  = sG[w][in0[lev] + 2 * p];
            const float* Bm = sG[w][in0[lev] + 2 * p + 1];
            float* C = sG[w][out0[lev] + p];
            float c[25];
            float ss = 0.0f;
            #pragma unroll
            for (int j = 0; j < 25; ++j) {
                const int idx = lg * 25 + j;
                const int l = idx / 10, h = idx % 10;
                float acc = 0.0f;
                #pragma unroll
                for (int k = 0; k < 10; ++k)
                    acc = fmaf(A[l * 10 + k], Bm[k * 10 + h], acc);
                c[j] = acc;
                ss = fmaf(acc, acc, ss);
            }
            ss += __shfl_xor_sync(gm, ss, 1);
            ss += __shfl_xor_sync(gm, ss, 2);
            ss = fmaxf(ss, 1e-24f);
            const float inv = rsqrtf(ss);
            if (lg == 0) logacc += 0.5f * __logf(ss);
            #pragma unroll
            for (int j = 0; j < 25; ++j) C[lg * 25 + j] = c[j] * inv;
        }
        __syncwarp();
    }

    // Head vector from core0 + x[b,0], applied to final matrix (slot 6).
    const float x0 = x[(size_t)b * NPIX];
    float wv = 0.0f;
    if (lane < 10) {
        #pragma unroll
        for (int l = 0; l < 10; ++l) {
            const float v0l = fmaf(x0, core0[10 + l] - core0[l], core0[l]);
            wv = fmaf(v0l, sG[w][6][l * 10 + lane], wv);
        }
    }
    float sq = (lane < 10) ? wv * wv : 0.0f;
    #pragma unroll
    for (int o = 16; o >= 1; o >>= 1) sq += __shfl_xor_sync(0xffffffffu, sq, o);
    #pragma unroll
    for (int o = 16; o >= 1; o >>= 1) logacc += __shfl_xor_sync(0xffffffffu, logacc, o);

    sq = fmaxf(sq, 1e-24f);
    const float logtot = logacc + 0.5f * __logf(sq);
    const float inv = rsqrtf(sq);
    if (lane < 10) sW[w][lane] = wv * inv;
    __syncwarp();

    if (lane < 10) {
        float acc = 0.0f;
        #pragma unroll
        for (int h = 0; h < 10; ++h) acc = fmaf(sW[w][h], cls[lane * 10 + h], acc);
        out[(size_t)b * 10 + lane] = acc + logtot;
    }
}

// Empty kernels to pad the per-call launch count to 4 so the fixed
// `ncu -s 5 -c 1` capture lands on phase1 (launch #6) next round.
__global__ void dummyk() {}

extern "C" void kernel_launch(void* const* d_in, const int* in_sizes, int n_in,
                              void* d_out, int out_size) {
    const float* x     = (const float*)d_in[0];   // (2048, 784)
    const float* core0 = (const float*)d_in[1];   // (1, 2, 10)
    const float* cm    = (const float*)d_in[2];   // (783, 10, 2, 10)
    const float* cls   = (const float*)d_in[3];   // (10, 10)
    float* out = (float*)d_out;                   // (2048, 10)

    dim3 g1(NSEG, BATCH / UPB);
    dummyk<<<1, 32>>>();
    phase1<<<g1, T1>>>(x, cm);
    combine<<<BATCH / CB, CB * 32>>>(x, core0, cls, out);
    dummyk<<<1, 32>>>();
}

// round 5
// speedup vs baseline: 1.2556x; 1.1697x over previous
#include <cuda_runtime.h>
#include <math.h>

#define BATCH   2048
#define NPIX    784
#define NMID    783      // number of mid cores
#define NSEG    16
#define LSEG    49       // NSEG*LSEG = 784 >= 783 (1 identity pad)
#define UPB     64       // batch units per block (phase 1)
#define T1      128      // threads per block (phase 1): 2 threads per unit
#define CB      4        // batches (warps) per block in combine
#define SLOT    105      // padded matrix slot (odd word stride -> bank spread)

// 4x pre-scale keeps segment-product norms in mid fp32 range (avoids the
// denormal-underflow -> EPS-clamp bias that broke round 2).
#define MSCALE      4.0f
#define SEG_LOGCOMP 67.92842369489701f   // LSEG * ln(4), subtracted exactly

typedef unsigned long long u64;

// Scratch: per (segment, batch) normalized 10x10 product + log norm
__device__ __align__(16) float g_G[(size_t)NSEG * BATCH * 100];  // [seg][b][l*10+h]
__device__ float g_logn[NSEG * BATCH];                            // [seg][b]

// ---- packed f32x2 helpers (FFMA2 path; see SASS_QUICKREF) ----
__device__ __forceinline__ u64 ffma2(u64 a, u64 b, u64 c) {
    u64 d; asm("fma.rn.f32x2 %0, %1, %2, %3;" : "=l"(d) : "l"(a), "l"(b), "l"(c));
    return d;
}
__device__ __forceinline__ u64 fmul2(u64 a, u64 b) {
    u64 d; asm("mul.rn.f32x2 %0, %1, %2;" : "=l"(d) : "l"(a), "l"(b));
    return d;
}
__device__ __forceinline__ u64 pk2(float lo, float hi) {
    u64 r; asm("mov.b64 %0, {%1, %2};" : "=l"(r) : "f"(lo), "f"(hi));
    return r;
}
__device__ __forceinline__ void upk2(u64 v, float& lo, float& hi) {
    asm("mov.b64 {%0, %1}, %2;" : "=f"(lo), "=f"(hi) : "l"(v));
}

// One chain step: Q = P * M (this thread's 5 rows), M[k][h] = A[k][h] + x*D[k][h].
__device__ __forceinline__ void stepmul(const float* __restrict__ s, u64 xx,
                                        const u64 (&P)[5][5], u64 (&Q)[5][5]) {
    #pragma unroll
    for (int kp = 0; kp < 5; ++kp) {
        const u64* a0 = reinterpret_cast<const u64*>(s + (2 * kp) * 24);
        const u64* d0 = reinterpret_cast<const u64*>(s + (2 * kp) * 24 + 12);
        const u64* a1 = reinterpret_cast<const u64*>(s + (2 * kp + 1) * 24);
        const u64* d1 = reinterpret_cast<const u64*>(s + (2 * kp + 1) * 24 + 12);
        u64 m0[5], m1[5];
        #pragma unroll
        for (int h = 0; h < 5; ++h) {
            m0[h] = ffma2(xx, d0[h], a0[h]);
            m1[h] = ffma2(xx, d1[h], a1[h]);
        }
        #pragma unroll
        for (int l = 0; l < 5; ++l) {
            float p0, p1;
            upk2(P[l][kp], p0, p1);
            const u64 pp0 = pk2(p0, p0);
            const u64 pp1 = pk2(p1, p1);
            if (kp == 0) {
                #pragma unroll
                for (int h = 0; h < 5; ++h) Q[l][h] = fmul2(pp0, m0[h]);
            } else {
                #pragma unroll
                for (int h = 0; h < 5; ++h) Q[l][h] = ffma2(pp0, m0[h], Q[l][h]);
            }
            #pragma unroll
            for (int h = 0; h < 5; ++h) Q[l][h] = ffma2(pp1, m1[h], Q[l][h]);
        }
    }
}

// Phase 1: per (batch, segment) normalized product of the segment's matrices.
__global__ void __launch_bounds__(T1, 3)
phase1(const float* __restrict__ x, const float* __restrict__ cm) {
    __shared__ __align__(16) float sAD[LSEG * 240];

    const int seg = blockIdx.x;
    const int n0  = seg * LSEG;

    for (int idx = threadIdx.x; idx < LSEG * 200; idx += T1) {
        const int step = idx / 200;
        const int r    = idx % 200;
        const int k    = r / 20;
        const int j    = r % 20;
        const int n    = n0 + step;
        float val;
        if (n < NMID) {
            const int base = ((n * 10 + k) * 2) * 10;
            if (j < 10) val = MSCALE * cm[base + j];
            else        val = MSCALE * (cm[base + 10 + (j - 10)] - cm[base + (j - 10)]);
        } else {
            val = (j < 10) ? ((j == k) ? MSCALE : 0.0f) : 0.0f;
        }
        sAD[step * 240 + k * 24 + ((j < 10) ? j : (j - 10 + 12))] = val;
    }
    __syncthreads();

    const int t    = threadIdx.x;
    const int unit = t >> 1;
    const int half = t & 1;
    const int b    = blockIdx.y * UPB + unit;
    const float* xb = x + (size_t)b * NPIX;

    u64 P[5][5], Q[5][5];

    {
        const float xv = xb[min(n0 + 1, NPIX - 1)];
        const u64 xx = pk2(xv, xv);
        #pragma unroll
        for (int l = 0; l < 5; ++l) {
            const u64* ar = reinterpret_cast<const u64*>(sAD + (half * 5 + l) * 24);
            const u64* dr = reinterpret_cast<const u64*>(sAD + (half * 5 + l) * 24 + 12);
            #pragma unroll
            for (int hp = 0; hp < 5; ++hp) P[l][hp] = ffma2(xx, dr[hp], ar[hp]);
        }
    }

    float xc = xb[min(n0 + 2, NPIX - 1)];
    #pragma unroll 1
    for (int st = 1; st < LSEG; st += 2) {
        const float xn1 = xb[min(n0 + st + 2, NPIX - 1)];
        const float xn2 = xb[min(n0 + st + 3, NPIX - 1)];
        stepmul(sAD + st * 240, pk2(xc, xc), P, Q);
        stepmul(sAD + (st + 1) * 240, pk2(xn1, xn1), Q, P);
        xc = xn2;
    }

    u64 ss2 = 0ull;
    #pragma unroll
    for (int l = 0; l < 5; ++l)
        #pragma unroll
        for (int hp = 0; hp < 5; ++hp) ss2 = ffma2(P[l][hp], P[l][hp], ss2);
    float slo, shi;
    upk2(ss2, slo, shi);
    float ss = slo + shi;
    ss += __shfl_xor_sync(0xffffffffu, ss, 1);
    ss = fmaxf(ss, 1e-24f);

    const float inv = rsqrtf(ss);
    const u64 ii = pk2(inv, inv);

    float* gp = g_G + ((size_t)seg * BATCH + b) * 100 + half * 50;
    #pragma unroll
    for (int l = 0; l < 5; ++l)
        #pragma unroll
        for (int hp = 0; hp < 5; ++hp)
            *reinterpret_cast<u64*>(gp + l * 10 + 2 * hp) = fmul2(P[l][hp], ii);
    if (half == 0)
        g_logn[seg * BATCH + b] = 0.5f * __logf(ss) - SEG_LOGCOMP;
}

// Combine: one warp per batch. Binary-tree reduction 16->8->4->2->1.
// Rewritten to be LDS-lean: per product, L = 32/cnt lanes; lane lg owns the
// strided column set {lg, lg+L, lg+2L} (<10). Per k-step: A[l][k] is a
// broadcast load within the lane group (conflict-free), B needs <=3 loads.
// Slots padded to SLOT=105 words so the 8 product bases hit distinct banks.
__global__ void __launch_bounds__(CB * 32)
combine(const float* __restrict__ x, const float* __restrict__ core0,
        const float* __restrict__ cls, float* __restrict__ out) {
    __shared__ float sG[CB][24][SLOT];  // slots 0..15 in, tree ping-pongs
    __shared__ float sW[CB][10];

    const int w    = threadIdx.x >> 5;
    const int lane = threadIdx.x & 31;
    const int b    = blockIdx.x * CB + w;

    float logacc = 0.0f;

    // Load 16 segment matrices + logs; zero the slot padding once.
    #pragma unroll
    for (int s = 0; s < NSEG; ++s) {
        const float* src = g_G + ((size_t)s * BATCH + b) * 100;
        #pragma unroll
        for (int i = lane; i < 100; i += 32) sG[w][s][i] = src[i];
    }
    #pragma unroll
    for (int s = 0; s < 24; ++s)
        if (lane < SLOT - 100) sG[w][s][100 + lane] = 0.0f;
    if (lane < NSEG) logacc = g_logn[lane * BATCH + b];
    __syncwarp();

    // Tree levels: (in, out, count)
    const int in0[4]  = {0, 16, 0, 4};
    const int out0[4] = {16, 0, 4, 6};
    const int cnt[4]  = {8, 4, 2, 1};

    #pragma unroll
    for (int lev = 0; lev < 4; ++lev) {
        const int L  = 32 / cnt[lev];            // lanes per product
        const int p  = lane / L;
        const int lg = lane % L;
        const unsigned gm = (L == 32) ? 0xffffffffu
                                      : (((1u << L) - 1u) << (p * L));
        const float* A  = sG[w][in0[lev] + 2 * p];
        const float* Bm = sG[w][in0[lev] + 2 * p + 1];
        float* C = sG[w][out0[lev] + p];

        // This lane's columns: h = lg + i*L, i = 0..2 (valid if < 10).
        bool  vld[3];
        int   hx[3];
        #pragma unroll
        for (int i = 0; i < 3; ++i) {
            const int h = lg + i * L;
            vld[i] = (h < 10);
            hx[i]  = vld[i] ? h : 0;
        }

        float c[10][3];
        #pragma unroll
        for (int l = 0; l < 10; ++l)
            #pragma unroll
            for (int i = 0; i < 3; ++i) c[l][i] = 0.0f;

        #pragma unroll
        for (int k = 0; k < 10; ++k) {
            float bk[3];
            #pragma unroll
            for (int i = 0; i < 3; ++i) bk[i] = Bm[k * 10 + hx[i]];
            #pragma unroll
            for (int l = 0; l < 10; ++l) {
                const float av = A[l * 10 + k];   // broadcast in lane group
                #pragma unroll
                for (int i = 0; i < 3; ++i) c[l][i] = fmaf(av, bk[i], c[l][i]);
            }
        }

        float ss = 0.0f;
        #pragma unroll
        for (int l = 0; l < 10; ++l)
            #pragma unroll
            for (int i = 0; i < 3; ++i)
                if (vld[i]) ss = fmaf(c[l][i], c[l][i], ss);
        #pragma unroll
        for (int off = 16; off >= 1; off >>= 1)
            if (off < L) ss += __shfl_xor_sync(gm, ss, off);

        ss = fmaxf(ss, 1e-24f);
        const float inv = rsqrtf(ss);
        if (lg == 0) logacc += 0.5f * __logf(ss);

        #pragma unroll
        for (int l = 0; l < 10; ++l)
            #pragma unroll
            for (int i = 0; i < 3; ++i)
                if (vld[i]) C[l * 10 + lg + i * L] = c[l][i] * inv;
        __syncwarp();
    }

    // Head vector from core0 + x[b,0], applied to final matrix (slot 6).
    const float x0 = x[(size_t)b * NPIX];
    float wv = 0.0f;
    if (lane < 10) {
        #pragma unroll
        for (int l = 0; l < 10; ++l) {
            const float v0l = fmaf(x0, core0[10 + l] - core0[l], core0[l]);
            wv = fmaf(v0l, sG[w][6][l * 10 + lane], wv);
        }
    }
    float sq = (lane < 10) ? wv * wv : 0.0f;
    #pragma unroll
    for (int o = 16; o >= 1; o >>= 1) sq += __shfl_xor_sync(0xffffffffu, sq, o);
    #pragma unroll
    for (int o = 16; o >= 1; o >>= 1) logacc += __shfl_xor_sync(0xffffffffu, logacc, o);

    sq = fmaxf(sq, 1e-24f);
    const float logtot = logacc + 0.5f * __logf(sq);
    const float inv = rsqrtf(sq);
    if (lane < 10) sW[w][lane] = wv * inv;
    __syncwarp();

    if (lane < 10) {
        float acc = 0.0f;
        #pragma unroll
        for (int h = 0; h < 10; ++h) acc = fmaf(sW[w][h], cls[lane * 10 + h], acc);
        out[(size_t)b * 10 + lane] = acc + logtot;
    }
}

extern "C" void kernel_launch(void* const* d_in, const int* in_sizes, int n_in,
                              void* d_out, int out_size) {
    const float* x     = (const float*)d_in[0];   // (2048, 784)
    const float* core0 = (const float*)d_in[1];   // (1, 2, 10)
    const float* cm    = (const float*)d_in[2];   // (783, 10, 2, 10)
    const float* cls   = (const float*)d_in[3];   // (10, 10)
    float* out = (float*)d_out;                   // (2048, 10)

    dim3 g1(NSEG, BATCH / UPB);
    phase1<<<g1, T1>>>(x, cm);
    combine<<<BATCH / CB, CB * 32>>>(x, core0, cls, out);
}